// round 1
// baseline (speedup 1.0000x reference)
#include <cuda_runtime.h>
#include <math_constants.h>

#define NBINS 512
#define KNN   16
#define BATCH 8192
#define NROWS 100000

// Scratch (allocation-free rule: __device__ globals)
__device__ float  g_bcol[NBINS];
__device__ double g_sum;

__global__ void zero_kernel() {
    int t = threadIdx.x;
    g_bcol[t] = 0.0f;
    if (t == 0) g_sum = 0.0;
}

// Column sums of outputs[0:BATCH, :]. Block g handles 128 rows, thread = column.
__global__ void colsum_kernel(const float* __restrict__ outputs) {
    int col = threadIdx.x;
    int r0  = blockIdx.x * 128;
    float acc = 0.0f;
#pragma unroll 8
    for (int r = 0; r < 128; r++)
        acc += outputs[(size_t)(r0 + r) * NBINS + col];
    atomicAdd(&g_bcol[col], acc);
}

// One block per batch row b. Base row cached in SMEM; warp w computes
// add[b,w] = max_j (outputs[nns[b,w], j] + outputs[b, j]).
__global__ __launch_bounds__(512, 4)
void main_kernel(const float* __restrict__ outputs,
                 const float* __restrict__ y,
                 const float* __restrict__ weights,
                 float* __restrict__ booster) {
    __shared__ __align__(16) float base[NBINS];
    __shared__ float s_add[KNN];

    int b    = blockIdx.x;
    int tid  = threadIdx.x;
    int warp = tid >> 5;
    int lane = tid & 31;

    // Load base row (coalesced, one float per thread)
    base[tid] = outputs[(size_t)b * NBINS + tid];
    __syncthreads();

    // Each warp handles one neighbor k = warp
    int idx = (int)y[b * KNN + warp];   // trunc toward zero; y >= 0
    const float4* g4 = (const float4*)(outputs + (size_t)idx * NBINS);
    const float4* b4 = (const float4*)base;

    float m = -CUDART_INF_F;
#pragma unroll
    for (int t = 0; t < 4; t++) {
        float4 a = g4[t * 32 + lane];
        float4 c = b4[t * 32 + lane];
        m = fmaxf(m, fmaxf(fmaxf(a.x + c.x, a.y + c.y),
                           fmaxf(a.z + c.z, a.w + c.w)));
    }
#pragma unroll
    for (int o = 16; o; o >>= 1)
        m = fmaxf(m, __shfl_xor_sync(0xFFFFFFFFu, m, o));
    if (lane == 0) s_add[warp] = m;
    __syncthreads();

    if (tid == 0) {
        float s = 0.0f;
#pragma unroll
        for (int k = 0; k < KNN; k++) s += s_add[k];
        booster[b] = fmaxf(0.5f, (2.0f - s * (1.0f / KNN)) * 0.5f);
        atomicAdd(&g_sum, (double)(s * weights[b]));
    }
}

// Scalar epilogue: b = max(b_col) - min(b_col); cost/diff/ratio.
__global__ void final_kernel(float* __restrict__ out) {
    __shared__ float smax[NBINS];
    __shared__ float smin[NBINS];
    int t = threadIdx.x;
    float v = g_bcol[t];
    smax[t] = v;
    smin[t] = v;
    __syncthreads();
#pragma unroll
    for (int s = 256; s; s >>= 1) {
        if (t < s) {
            smax[t] = fmaxf(smax[t], smax[t + s]);
            smin[t] = fminf(smin[t], smin[t + s]);
        }
        __syncthreads();
    }
    if (t == 0) {
        float bb       = smax[0] - smin[0];
        float target_b = (float)NROWS / (float)NBINS;
        float ratio    = bb / target_b;
        float add_mean = (float)(g_sum / (double)(BATCH * KNN));
        float d        = 2.0f - add_mean;
        d = d * d;
        out[0] = ratio + d;  // cost
        out[1] = d;          // diff
        out[2] = ratio;      // b / target_b
    }
}

extern "C" void kernel_launch(void* const* d_in, const int* in_sizes, int n_in,
                              void* d_out, int out_size) {
    const float* outputs = (const float*)d_in[0];
    const float* y       = (const float*)d_in[1];
    const float* weights = (const float*)d_in[2];
    float* out = (float*)d_out;

    zero_kernel<<<1, NBINS>>>();
    colsum_kernel<<<BATCH / 128, NBINS>>>(outputs);
    main_kernel<<<BATCH, NBINS>>>(outputs, y, weights, out + 3);
    final_kernel<<<1, NBINS>>>(out);
}